// round 8
// baseline (speedup 1.0000x reference)
#include <cuda_runtime.h>
#include <math.h>
#include <float.h>
#include <stdint.h>

// MoE gate: logits = hidden @ gate^T ; softmax over 8 experts; top-2; renormalize.
// hidden: [T, 4096] f32 (T = 16384), gate: [8, 4096] f32.
// Output (flattened f32): [T*2] topk weights, then [T*2] expert indices (as float).
//
// Architecture:
//  - Prepass kernel packs gate into expert-pair-interleaved, tile-transposed
//    layout so the main loop can use packed fma.rn.f32x2 (FFMA2) and read gate
//    with single-line coalesced, 4x-warp-deduplicated loads.
//  - Main kernel: lane = (grp = lane>>3, j = lane&7). Each grp owns 2 tokens;
//    8 j-lanes cover 8 consecutive float4 of h per iter. Gate addresses are
//    identical across grps (4-way dedup -> 1 L1 line per gate LDG.128).
//    acc = 2 tokens x 4 expert-pairs of f32x2 (16 regs).
//  - H split in half across warp pairs; 128-thr blocks, grid=1024 = single wave.

#define NEXP   8
#define HDIM   4096
#define HV     (HDIM / 4)      // 1024 float4 per row
#define HSPLIT 2
#define HHV    (HV / HSPLIT)   // 512 float4 per half
#define ITERS  (HHV / 8)       // 64 iters (8 float4 of h per iter)
#define NTILES (HV / 8)        // 128 one-KB gate tiles
#define TOK_PER_BLOCK 16

// Packed gate scratch: tile t (8 float4 of h), chunk layout [i=0..7][j=0..7]:
//   chunk(i,j) is 16B = float4( g[2epb][h], g[2epb+1][h], g[2epb+2][h], g[2epb+3][h] )
//   with s = i>>1, epb = (i&1)*2, h = (t*8+j)*4 + s.
// As ulonglong2: .x = pair(e_{2epb}, e_{2epb+1}), .y = pair(e_{2epb+2}, e_{2epb+3}).
__device__ float4 g_packed[NTILES * 64];   // 128 KB

__global__ void pack_gate_kernel(const float* __restrict__ gate)
{
    const int tid = blockIdx.x * blockDim.x + threadIdx.x;
    if (tid >= NTILES * 64) return;
    const int t = tid >> 6, r = tid & 63, i = r >> 3, j = r & 7;
    const int s = i >> 1, epb = (i & 1) * 2;
    const int h = (t * 8 + j) * 4 + s;
    float4 v;
    v.x = gate[(2 * epb + 0) * HDIM + h];
    v.y = gate[(2 * epb + 1) * HDIM + h];
    v.z = gate[(2 * epb + 2) * HDIM + h];
    v.w = gate[(2 * epb + 3) * HDIM + h];
    g_packed[t * 64 + i * 8 + j] = v;
}

#define FMA2(acc, a, b) \
    asm("fma.rn.f32x2 %0, %1, %2, %0;" : "+l"(acc) : "l"(a), "l"(b))
#define ADD2(d, a, b) \
    asm("add.rn.f32x2 %0, %1, %2;" : "=l"(d) : "l"(a), "l"(b))
#define PACK_DUP2(o, f) \
    asm("mov.b64 %0, {%1, %1};" : "=l"(o) : "r"(__float_as_uint(f)))
#define UNPACK2(lo, hi, v) \
    asm("mov.b64 {%0, %1}, %2;" : "=r"(lo), "=r"(hi) : "l"(v))

// one iteration's FFMA2 burst: 2 tokens x 4 scalars x 4 expert-pairs
#define COMPUTE(xv0, xv1, it)                                                  \
    do {                                                                       \
        const ulonglong2* gt = gpk + ((size_t)(tile0 + (it))) * 64 + j;        \
        const float* xf0 = &(xv0).x;                                           \
        const float* xf1 = &(xv1).x;                                           \
        _Pragma("unroll")                                                      \
        for (int s = 0; s < 4; s++) {                                          \
            const ulonglong2 gA = gt[(2 * s) * 8];                             \
            const ulonglong2 gB = gt[(2 * s + 1) * 8];                         \
            uint64_t p0, p1;                                                   \
            PACK_DUP2(p0, xf0[s]);                                             \
            PACK_DUP2(p1, xf1[s]);                                             \
            FMA2(acc[0][0], p0, gA.x); FMA2(acc[0][1], p0, gA.y);              \
            FMA2(acc[0][2], p0, gB.x); FMA2(acc[0][3], p0, gB.y);              \
            FMA2(acc[1][0], p1, gA.x); FMA2(acc[1][1], p1, gA.y);              \
            FMA2(acc[1][2], p1, gB.x); FMA2(acc[1][3], p1, gB.y);              \
        }                                                                      \
    } while (0)

#define LOAD_X(b0, b1, it)                          \
    do {                                            \
        b0 = __ldcs(&xb0[(size_t)(it) * 8]);        \
        b1 = __ldcs(&xb1[(size_t)(it) * 8]);        \
    } while (0)

__global__ __launch_bounds__(128, 7) void moe_gate_kernel(
    const float4* __restrict__ hid,
    float* __restrict__ out,
    int n_tokens)
{
    const int lane    = threadIdx.x & 31;
    const int w       = threadIdx.x >> 5;   // 0..3
    const int tokwarp = w >> 1;             // 0..1
    const int half    = w & 1;              // h-half
    const int grp     = lane >> 3;          // 0..3: token group within warp
    const int j       = lane & 7;           // h-sub position

    const int row0 = blockIdx.x * TOK_PER_BLOCK + tokwarp * 8 + grp * 2;
    if (row0 >= n_tokens) return;

    const ulonglong2* gpk = (const ulonglong2*)g_packed;
    const int tile0 = half * (HHV / 8);     // 64 tiles per half

    const float4* xb0 = hid + (size_t)(row0 + 0) * HV + half * HHV + j;
    const float4* xb1 = hid + (size_t)(row0 + 1) * HV + half * HHV + j;

    uint64_t acc[2][4];
    #pragma unroll
    for (int t = 0; t < 2; t++)
        #pragma unroll
        for (int ep = 0; ep < 4; ep++)
            acc[t][ep] = 0ull;

    float4 xa0, xa1, xc0, xc1;
    LOAD_X(xa0, xa1, 0);

    #pragma unroll 1
    for (int it = 0; it < ITERS - 2; it += 2) {
        LOAD_X(xc0, xc1, it + 1);
        COMPUTE(xa0, xa1, it);
        LOAD_X(xa0, xa1, it + 2);
        COMPUTE(xc0, xc1, it + 1);
    }
    {
        LOAD_X(xc0, xc1, ITERS - 1);
        COMPUTE(xa0, xa1, ITERS - 2);
        COMPUTE(xc0, xc1, ITERS - 1);
    }

    // reduce over the 8 j-lanes of each grp (masks 1,2,4 stay within the grp)
    #pragma unroll
    for (int t = 0; t < 2; t++)
        #pragma unroll
        for (int ep = 0; ep < 4; ep++) {
            uint64_t v = acc[t][ep], o;
            o = __shfl_xor_sync(0xffffffffu, (unsigned long long)v, 1); ADD2(v, v, o);
            o = __shfl_xor_sync(0xffffffffu, (unsigned long long)v, 2); ADD2(v, v, o);
            o = __shfl_xor_sync(0xffffffffu, (unsigned long long)v, 4); ADD2(v, v, o);
            acc[t][ep] = v;
        }

    __shared__ float part[2][HSPLIT][8][NEXP];   // [tokwarp][half][token][expert]
    if (j == 0) {
        #pragma unroll
        for (int t = 0; t < 2; t++)
            #pragma unroll
            for (int ep = 0; ep < 4; ep++) {
                unsigned lo, hi;
                UNPACK2(lo, hi, acc[t][ep]);
                part[tokwarp][half][grp * 2 + t][2 * ep + 0] = __uint_as_float(lo);
                part[tokwarp][half][grp * 2 + t][2 * ep + 1] = __uint_as_float(hi);
            }
    }
    __syncthreads();

    // finalize: half-0 warps, lanes 0..7 -> one token each
    if (half == 0 && lane < 8) {
        const int token = blockIdx.x * TOK_PER_BLOCK + tokwarp * 8 + lane;

        float l[NEXP];
        #pragma unroll
        for (int q = 0; q < NEXP; q++)
            l[q] = part[tokwarp][0][lane][q] + part[tokwarp][1][lane][q];

        // top-1 (strict > keeps lowest index on ties, matching lax.top_k)
        float b0 = l[0]; int i0 = 0;
        #pragma unroll
        for (int q = 1; q < NEXP; q++)
            if (l[q] > b0) { b0 = l[q]; i0 = q; }

        // top-2
        float b1 = -FLT_MAX; int i1 = 0;
        #pragma unroll
        for (int q = 0; q < NEXP; q++)
            if (q != i0 && l[q] > b1) { b1 = l[q]; i1 = q; }

        // renormalized top-2 softmax: w0 = e^{l0} / (e^{l0} + e^{l1})
        const float w0 = 1.0f / (1.0f + expf(b1 - b0));
        const float w1 = 1.0f - w0;

        float* out_idx = out + (size_t)n_tokens * 2;
        out[token * 2 + 0] = w0;
        out[token * 2 + 1] = w1;
        out_idx[token * 2 + 0] = (float)i0;
        out_idx[token * 2 + 1] = (float)i1;
    }
}

extern "C" void kernel_launch(void* const* d_in, const int* in_sizes, int n_in,
                              void* d_out, int out_size)
{
    const float* hid  = (const float*)d_in[0];   // hidden_states
    const float* gate = (const float*)d_in[1];   // gate_weight
    float* out = (float*)d_out;

    const int n_tokens = in_sizes[0] / HDIM;     // 16384

    pack_gate_kernel<<<(NTILES * 64 + 255) / 256, 256>>>(gate);

    const int blocks = (n_tokens + TOK_PER_BLOCK - 1) / TOK_PER_BLOCK;  // 1024
    moe_gate_kernel<<<blocks, 128>>>((const float4*)hid, out, n_tokens);
}